// round 13
// baseline (speedup 1.0000x reference)
#include <cuda_runtime.h>
#include <cuda_bf16.h>
#include <cstdint>

#define BATCH 2
#define SEQ   2048
#define DM    1024
#define NH    16
#define HD    64
#define MROWS (BATCH*SEQ)
#define K3    (3*DM)

typedef __nv_bfloat16 bf16;

// ---------------------------------------------------------------------------
// Scratch (allocation-free rule: __device__ globals)
// ---------------------------------------------------------------------------
__device__ float g_V[BATCH*NH*SEQ*HD];
__device__ bf16 g_X3[(size_t)MROWS*K3];
__device__ bf16 g_W3[(size_t)4*DM*K3];
__device__ bf16 g_A3[(size_t)MROWS*K3];
__device__ bf16 g_Qh[BATCH*NH*SEQ*HD];
__device__ bf16 g_Ql[BATCH*NH*SEQ*HD];
__device__ bf16 g_Kh[BATCH*NH*SEQ*HD];
__device__ bf16 g_Kl[BATCH*NH*SEQ*HD];
__device__ bf16 g_Vth[BATCH*NH*HD*SEQ];
__device__ bf16 g_Vtl[BATCH*NH*HD*SEQ];

// ---------------------------------------------------------------------------
// helpers
// ---------------------------------------------------------------------------
#define CP_ASYNC16(dst, src) \
    asm volatile("cp.async.cg.shared.global [%0], [%1], 16;" :: "r"(dst), "l"(src))
#define CP_COMMIT() asm volatile("cp.async.commit_group;" ::: "memory")
#define CP_WAIT1()  asm volatile("cp.async.wait_group 1;" ::: "memory")

__device__ __forceinline__ uint32_t smem_u32(const void* p) {
    uint32_t a;
    asm("{ .reg .u64 t; cvta.to.shared.u64 t, %1; cvt.u32.u64 %0, t; }" : "=r"(a) : "l"(p));
    return a;
}
__device__ __forceinline__ void ldmx4(uint32_t* r, uint32_t addr) {
    asm volatile("ldmatrix.sync.aligned.m8n8.x4.shared.b16 {%0,%1,%2,%3}, [%4];"
                 : "=r"(r[0]), "=r"(r[1]), "=r"(r[2]), "=r"(r[3]) : "r"(addr));
}
__device__ __forceinline__ void mma_bf16(float* c, const uint32_t* a, const uint32_t* b) {
    asm volatile(
        "mma.sync.aligned.m16n8k16.row.col.f32.bf16.bf16.f32 "
        "{%0,%1,%2,%3}, {%4,%5,%6,%7}, {%8,%9}, {%0,%1,%2,%3};"
        : "+f"(c[0]), "+f"(c[1]), "+f"(c[2]), "+f"(c[3])
        : "r"(a[0]), "r"(a[1]), "r"(a[2]), "r"(a[3]), "r"(b[0]), "r"(b[1]));
}
__device__ __forceinline__ uint32_t pack2bf(float lo, float hi) {
    uint32_t r;
    asm("cvt.rn.bf16x2.f32 %0, %1, %2;" : "=r"(r) : "f"(hi), "f"(lo));
    return r;
}

// ---------------------------------------------------------------------------
// fp32 -> triple-interleaved bf16 (A-type for activations)
// ---------------------------------------------------------------------------
__global__ void split3_a(const float* __restrict__ src,
                         bf16* __restrict__ dst, int n2)
{
    int i = blockIdx.x * blockDim.x + threadIdx.x;
    int stride = gridDim.x * blockDim.x;
    __nv_bfloat162* d2 = (__nv_bfloat162*)dst;
    for (; i < n2; i += stride) {
        float2 x = ((const float2*)src)[i];
        bf16 hx = __float2bfloat16(x.x);
        bf16 hy = __float2bfloat16(x.y);
        bf16 lx = __float2bfloat16(x.x - __bfloat162float(hx));
        bf16 ly = __float2bfloat16(x.y - __bfloat162float(hy));
        d2[i*3+0] = __halves2bfloat162(hx, lx);
        d2[i*3+1] = __halves2bfloat162(hx, hy);
        d2[i*3+2] = __halves2bfloat162(ly, hy);
    }
}

// all 4 weights, B-type triple, one launch
struct W4 { const float* p[4]; };
__global__ void split3_w(W4 ws, bf16* __restrict__ dst)
{
    const float* src = ws.p[blockIdx.y];
    __nv_bfloat162* d2 = (__nv_bfloat162*)(dst + (size_t)blockIdx.y * DM * K3);
    const int n2 = DM * DM / 2;
    int i = blockIdx.x * blockDim.x + threadIdx.x;
    int stride = gridDim.x * blockDim.x;
    for (; i < n2; i += stride) {
        float2 x = ((const float2*)src)[i];
        bf16 hx = __float2bfloat16(x.x);
        bf16 hy = __float2bfloat16(x.y);
        bf16 lx = __float2bfloat16(x.x - __bfloat162float(hx));
        bf16 ly = __float2bfloat16(x.y - __bfloat162float(hy));
        d2[i*3+0] = __halves2bfloat162(hx, hx);
        d2[i*3+1] = __halves2bfloat162(lx, hy);
        d2[i*3+2] = __halves2bfloat162(hy, ly);
    }
}

// V [bh, s, d] fp32 -> Vt hi/lo [bh, d, s] bf16 (64x64 tile transpose)
__global__ void transpose_split_v(const float* __restrict__ V,
                                  bf16* __restrict__ vth, bf16* __restrict__ vtl)
{
    __shared__ float ts[64][65];
    const int bh = blockIdx.y;
    const int s0 = blockIdx.x * 64;
    const int t = threadIdx.x;
    #pragma unroll
    for (int i = 0; i < 4; i++) {
        int lin = t + i * 256;
        int r = lin >> 4, c = (lin & 15) * 4;
        float4 v = *(const float4*)(V + ((size_t)(bh * SEQ + s0 + r)) * HD + c);
        ts[r][c] = v.x; ts[r][c+1] = v.y; ts[r][c+2] = v.z; ts[r][c+3] = v.w;
    }
    __syncthreads();
    const int d = t >> 2, sseg = (t & 3) * 16;
    size_t ob = ((size_t)(bh * HD + d)) * SEQ + s0 + sseg;
    #pragma unroll
    for (int u = 0; u < 16; u += 2) {
        float v0 = ts[sseg + u][d], v1 = ts[sseg + u + 1][d];
        bf16 h0 = __float2bfloat16(v0), h1 = __float2bfloat16(v1);
        *(__nv_bfloat162*)(vth + ob + u) = __halves2bfloat162(h0, h1);
        *(__nv_bfloat162*)(vtl + ob + u) = __halves2bfloat162(
            __float2bfloat16(v0 - __bfloat162float(h0)),
            __float2bfloat16(v1 - __bfloat162float(h1)));
    }
}

// ---------------------------------------------------------------------------
// bf16 HMMA GEMM: C = A3[M,K3] * B3[N,K3]^T, CTA tile 256x128, warp 64x64,
// 3-stage cp.async pipeline (48KB/stage). 8 warps 4(M) x 2(N).
// MODE 0: fp32 row-major [M, DM]
// MODE 1: fp32 head layout [b,h,s,d]
// MODE 2: (hi,lo) bf16 head layout, scaled (for Q/K)
// ---------------------------------------------------------------------------
#define GEMM_STAGE_SZ 49152
#define GEMM_SMEM     (3 * GEMM_STAGE_SZ)

template<int MODE>
__global__ void __launch_bounds__(256, 1)
gemm_hmma(const bf16* __restrict__ A3, const bf16* __restrict__ B3,
          float* __restrict__ Cf, bf16* __restrict__ Chi,
          bf16* __restrict__ Clo, float scale)
{
    extern __shared__ char dsm[];
    const uint32_t sb = smem_u32(dsm);
    const int t = threadIdx.x;
    const int lane = t & 31, wid = t >> 5;
    const int wm = wid & 3, wn = wid >> 2;
    const int m0 = blockIdx.y << 8, n0 = blockIdx.x << 7;
    const int matA = lane >> 3, lr = lane & 7;

    float acc[4][8][4];
    #pragma unroll
    for (int mi = 0; mi < 4; mi++)
        #pragma unroll
        for (int ni = 0; ni < 8; ni++)
            #pragma unroll
            for (int j = 0; j < 4; j++) acc[mi][ni][j] = 0.f;

    auto load_stage = [&](int slot, int kt) {
        const uint32_t sa  = sb + (uint32_t)slot * GEMM_STAGE_SZ;
        const uint32_t sbm = sa + 32768u;
        const int k0 = kt << 6;
        #pragma unroll
        for (int i = 0; i < 8; i++) {           // A: 256 rows
            const int lin = t + (i << 8);
            const int row = lin >> 3, c8 = lin & 7;
            const uint32_t soff = (uint32_t)(row * 128 + ((c8 ^ (row & 7)) << 4));
            CP_ASYNC16(sa + soff, A3 + (size_t)(m0 + row) * K3 + k0 + c8 * 8);
        }
        #pragma unroll
        for (int i = 0; i < 4; i++) {           // B: 128 rows
            const int lin = t + (i << 8);
            const int row = lin >> 3, c8 = lin & 7;
            const uint32_t soff = (uint32_t)(row * 128 + ((c8 ^ (row & 7)) << 4));
            CP_ASYNC16(sbm + soff, B3 + (size_t)(n0 + row) * K3 + k0 + c8 * 8);
        }
    };

    const int NIT = K3 / 64;                    // 48
    load_stage(0, 0); CP_COMMIT();
    load_stage(1, 1); CP_COMMIT();

    for (int kt = 0; kt < NIT; kt++) {
        CP_WAIT1();
        __syncthreads();
        const int slot = kt % 3;
        if (kt + 2 < NIT) load_stage((kt + 2) % 3, kt + 2);
        CP_COMMIT();

        const uint32_t sa  = sb + (uint32_t)slot * GEMM_STAGE_SZ;
        const uint32_t sbm = sa + 32768u;

        #pragma unroll
        for (int ks = 0; ks < 4; ks++) {
            uint32_t a[4][4];
            #pragma unroll
            for (int mi = 0; mi < 4; mi++) {
                const int r = wm * 64 + mi * 16 + ((matA & 1) << 3) + lr;
                const int ch = ks * 2 + (matA >> 1);
                ldmx4(a[mi], sa + (uint32_t)(r * 128 + ((ch ^ (r & 7)) << 4)));
            }
            uint32_t bf[8][2];
            #pragma unroll
            for (int np = 0; np < 4; np++) {
                const int r = wn * 64 + np * 16 + ((matA >> 1) << 3) + lr;
                const int ch = ks * 2 + (matA & 1);
                uint32_t q[4];
                ldmx4(q, sbm + (uint32_t)(r * 128 + ((ch ^ (r & 7)) << 4)));
                bf[np*2+0][0] = q[0]; bf[np*2+0][1] = q[1];
                bf[np*2+1][0] = q[2]; bf[np*2+1][1] = q[3];
            }
            #pragma unroll
            for (int mi = 0; mi < 4; mi++)
                #pragma unroll
                for (int ni = 0; ni < 8; ni++)
                    mma_bf16(acc[mi][ni], a[mi], bf[ni]);
        }
        __syncthreads();
    }

    const int tr = lane >> 2, tc = (lane & 3) << 1;
    #pragma unroll
    for (int mi = 0; mi < 4; mi++) {
        #pragma unroll
        for (int ni = 0; ni < 8; ni++) {
            const int row = m0 + wm * 64 + mi * 16 + tr;
            const int col = n0 + wn * 64 + ni * 8 + tc;
            #pragma unroll
            for (int half = 0; half < 2; half++) {
                const int rr = row + half * 8;
                const float v0 = acc[mi][ni][half*2+0];
                const float v1 = acc[mi][ni][half*2+1];
                if (MODE == 0) {
                    *(float2*)(Cf + (size_t)rr * DM + col) = make_float2(v0, v1);
                } else {
                    const int b = rr >> 11, s2 = rr & (SEQ - 1);
                    const int h = col >> 6,  d = col & (HD - 1);
                    const size_t idx = ((size_t)((b * NH + h) * SEQ + s2)) * HD + d;
                    if (MODE == 1) {
                        *(float2*)(Cf + idx) = make_float2(v0, v1);
                    } else {
                        const float x = v0 * scale, y = v1 * scale;
                        bf16 hx = __float2bfloat16(x), hy = __float2bfloat16(y);
                        *(__nv_bfloat162*)(Chi + idx) = __halves2bfloat162(hx, hy);
                        *(__nv_bfloat162*)(Clo + idx) = __halves2bfloat162(
                            __float2bfloat16(x - __bfloat162float(hx)),
                            __float2bfloat16(y - __bfloat162float(hy)));
                    }
                }
            }
        }
    }
}

// ---------------------------------------------------------------------------
// Tensor-core causal flash attention.
// CTA: 256 q-rows x 8 warps (warp = m32 x n64), k-tiles of 64.
// S = Qhi*Khi + Qhi*Klo + Qlo*Khi (Q pre-scaled by 1/8).
// O += Phi*Vhi + Phi*Vlo + Plo*Vhi (P split in registers).
// Output written directly as triple-interleaved A3 (for O-projection).
// ---------------------------------------------------------------------------
#define FA_SMEM (2*32768 + 2*32768)

__global__ void __launch_bounds__(256, 1)
flash_hmma(const bf16* __restrict__ Qh, const bf16* __restrict__ Ql,
           const bf16* __restrict__ Kh, const bf16* __restrict__ Kl,
           const bf16* __restrict__ Vth, const bf16* __restrict__ Vtl,
           bf16* __restrict__ A3out)
{
    extern __shared__ char dsmf[];
    const uint32_t sb = smem_u32(dsmf);
    const uint32_t sQh = sb, sQl = sb + 32768u;

    const int t = threadIdx.x;
    const int lane = t & 31, wid = t >> 5;
    const int matA = lane >> 3, lr = lane & 7;
    const int qt = 7 - blockIdx.x;            // big tiles first
    const int bh = blockIdx.y;
    const int qbase = qt * 256;
    const int wr = qbase + wid * 32;          // warp's first q row
    const int nkt = 4 * qt + 4;

    const size_t qoff = (size_t)(bh * SEQ + qbase) * HD;
    const size_t koff = (size_t)bh * SEQ * HD;
    const size_t voff = (size_t)bh * HD * SEQ;

    auto load_stage = [&](int slot, int kt) {
        const uint32_t st = sb + 65536u + (uint32_t)slot * 32768u;
        const int kb = kt * 64;
        #pragma unroll
        for (int i = 0; i < 2; i++) {
            const int lin = t + (i << 8);
            const int row = lin >> 3, c8 = lin & 7;
            const uint32_t soff = (uint32_t)(row * 128 + ((c8 ^ (row & 7)) << 4));
            CP_ASYNC16(st + soff,           Kh  + koff + (size_t)(kb + row) * HD + c8 * 8);
            CP_ASYNC16(st + 8192u  + soff,  Kl  + koff + (size_t)(kb + row) * HD + c8 * 8);
            CP_ASYNC16(st + 16384u + soff,  Vth + voff + (size_t)row * SEQ + kb + c8 * 8);
            CP_ASYNC16(st + 24576u + soff,  Vtl + voff + (size_t)row * SEQ + kb + c8 * 8);
        }
    };

    // Q tiles (256 rows, hi+lo), loaded once
    #pragma unroll
    for (int i = 0; i < 8; i++) {
        const int lin = t + (i << 8);
        const int row = lin >> 3, c8 = lin & 7;
        const uint32_t soff = (uint32_t)(row * 128 + ((c8 ^ (row & 7)) << 4));
        CP_ASYNC16(sQh + soff, Qh + qoff + (size_t)row * HD + c8 * 8);
        CP_ASYNC16(sQl + soff, Ql + qoff + (size_t)row * HD + c8 * 8);
    }
    load_stage(0, 0); CP_COMMIT();
    load_stage(1, 1); CP_COMMIT();

    float o[2][8][4];
    float m_[2][2], l_[2][2];
    #pragma unroll
    for (int mi = 0; mi < 2; mi++) {
        m_[mi][0] = -1e30f; m_[mi][1] = -1e30f;
        l_[mi][0] = 0.f;    l_[mi][1] = 0.f;
        #pragma unroll
        for (int ni = 0; ni < 8; ni++)
            #pragma unroll
            for (int j = 0; j < 4; j++) o[mi][ni][j] = 0.f;
    }

    for (int kt = 0; kt < nkt; kt++) {
        CP_WAIT1();
        __syncthreads();
        const int ktb = kt * 64;
        const uint32_t st = sb + 65536u + (uint32_t)(kt & 1) * 32768u;

        if (ktb <= wr + 31) {
            // ---- S = Q K^T ----
            float s[2][8][4];
            #pragma unroll
            for (int mi = 0; mi < 2; mi++)
                #pragma unroll
                for (int ni = 0; ni < 8; ni++)
                    #pragma unroll
                    for (int j = 0; j < 4; j++) s[mi][ni][j] = 0.f;

            #pragma unroll
            for (int ks = 0; ks < 4; ks++) {
                uint32_t ah[2][4], al[2][4];
                #pragma unroll
                for (int mi = 0; mi < 2; mi++) {
                    const int r = wid * 32 + mi * 16 + ((matA & 1) << 3) + lr;
                    const int ch = ks * 2 + (matA >> 1);
                    const uint32_t off = (uint32_t)(r * 128 + ((ch ^ (r & 7)) << 4));
                    ldmx4(ah[mi], sQh + off);
                    ldmx4(al[mi], sQl + off);
                }
                #pragma unroll
                for (int nb = 0; nb < 4; nb++) {
                    const int r2 = nb * 16 + ((matA >> 1) << 3) + lr;
                    const int ch2 = ks * 2 + (matA & 1);
                    const uint32_t off2 = (uint32_t)(r2 * 128 + ((ch2 ^ (r2 & 7)) << 4));
                    uint32_t kh4[4], kl4[4];
                    ldmx4(kh4, st + off2);
                    ldmx4(kl4, st + 8192u + off2);
                    #pragma unroll
                    for (int mi = 0; mi < 2; mi++) {
                        mma_bf16(s[mi][2*nb],   ah[mi], kh4);
                        mma_bf16(s[mi][2*nb+1], ah[mi], kh4 + 2);
                        mma_bf16(s[mi][2*nb],   ah[mi], kl4);
                        mma_bf16(s[mi][2*nb+1], ah[mi], kl4 + 2);
                        mma_bf16(s[mi][2*nb],   al[mi], kh4);
                        mma_bf16(s[mi][2*nb+1], al[mi], kh4 + 2);
                    }
                }
            }

            // ---- causal mask + online softmax per mi ----
            #pragma unroll
            for (int mi = 0; mi < 2; mi++) {
                const int row0 = wr + mi * 16 + (lane >> 2), row1 = row0 + 8;
                if (ktb + 63 > row0) {
                    #pragma unroll
                    for (int ni = 0; ni < 8; ni++) {
                        const int c0 = ktb + ni * 8 + ((lane & 3) << 1);
                        if (c0     > row0) s[mi][ni][0] = -1e9f;
                        if (c0 + 1 > row0) s[mi][ni][1] = -1e9f;
                        if (c0     > row1) s[mi][ni][2] = -1e9f;
                        if (c0 + 1 > row1) s[mi][ni][3] = -1e9f;
                    }
                }
                float rx0 = -1e30f, rx1 = -1e30f;
                #pragma unroll
                for (int ni = 0; ni < 8; ni++) {
                    rx0 = fmaxf(rx0, fmaxf(s[mi][ni][0], s[mi][ni][1]));
                    rx1 = fmaxf(rx1, fmaxf(s[mi][ni][2], s[mi][ni][3]));
                }
                rx0 = fmaxf(rx0, __shfl_xor_sync(0xffffffffu, rx0, 1));
                rx0 = fmaxf(rx0, __shfl_xor_sync(0xffffffffu, rx0, 2));
                rx1 = fmaxf(rx1, __shfl_xor_sync(0xffffffffu, rx1, 1));
                rx1 = fmaxf(rx1, __shfl_xor_sync(0xffffffffu, rx1, 2));
                const float nm0 = fmaxf(m_[mi][0], rx0), nm1 = fmaxf(m_[mi][1], rx1);
                const float a0 = __expf(m_[mi][0] - nm0), a1 = __expf(m_[mi][1] - nm1);
                float sum0 = 0.f, sum1 = 0.f;
                #pragma unroll
                for (int ni = 0; ni < 8; ni++) {
                    s[mi][ni][0] = __expf(s[mi][ni][0] - nm0);
                    s[mi][ni][1] = __expf(s[mi][ni][1] - nm0);
                    s[mi][ni][2] = __expf(s[mi][ni][2] - nm1);
                    s[mi][ni][3] = __expf(s[mi][ni][3] - nm1);
                    sum0 += s[mi][ni][0] + s[mi][ni][1];
                    sum1 += s[mi][ni][2] + s[mi][ni][3];
                }
                sum0 += __shfl_xor_sync(0xffffffffu, sum0, 1);
                sum0 += __shfl_xor_sync(0xffffffffu, sum0, 2);
                sum1 += __shfl_xor_sync(0xffffffffu, sum1, 1);
                sum1 += __shfl_xor_sync(0xffffffffu, sum1, 2);
                l_[mi][0] = l_[mi][0] * a0 + sum0;  m_[mi][0] = nm0;
                l_[mi][1] = l_[mi][1] * a1 + sum1;  m_[mi][1] = nm1;
                #pragma unroll
                for (int ni = 0; ni < 8; ni++) {
                    o[mi][ni][0] *= a0; o[mi][ni][1] *= a0;
                    o[mi][ni][2] *= a1; o[mi][ni][3] *= a1;
                }
            }

            // ---- O += P V (P in registers, hi/lo compensated) ----
            #pragma unroll
            for (int j = 0; j < 4; j++) {
                uint32_t pa_h[2][4], pa_l[2][4];
                #pragma unroll
                for (int mi = 0; mi < 2; mi++) {
                    #pragma unroll
                    for (int q2 = 0; q2 < 2; q2++) {
                        const float c0 = s[mi][2*j + q2][0], c1 = s[mi][2*j + q2][1];
                        const float c2 = s[mi][2*j + q2][2], c3 = s[mi][2*j + q2][3];
                        const uint32_t h01 = pack2bf(c0, c1);
                        const uint32_t h23 = pack2bf(c2, c3);
                        pa_h[mi][q2*2 + 0] = h01;
                        pa_h[mi][q2*2 + 1] = h23;
                        __nv_bfloat162 hb01 = *(__nv_bfloat162*)&h01;
                        __nv_bfloat162 hb23 = *(__nv_bfloat162*)&h23;
                        float2 f01 = __bfloat1622float2(hb01);
                        float2 f23 = __bfloat1622float2(hb23);
                        pa_l[mi][q2*2 + 0] = pack2bf(c0 - f01.x, c1 - f01.y);
                        pa_l[mi][q2*2 + 1] = pack2bf(c2 - f23.x, c3 - f23.y);
                    }
                }
                #pragma unroll
                for (int db = 0; db < 4; db++) {
                    const int r2 = db * 16 + ((matA >> 1) << 3) + lr;
                    const int ch2 = j * 2 + (matA & 1);
                    const uint32_t off2 = (uint32_t)(r2 * 128 + ((ch2 ^ (r2 & 7)) << 4));
                    uint32_t vh4[4], vl4[4];
                    ldmx4(vh4, st + 16384u + off2);
                    ldmx4(vl4, st + 24576u + off2);
                    #pragma unroll
                    for (int mi = 0; mi < 2; mi++) {
                        mma_bf16(o[mi][2*db],   pa_h[mi], vh4);
                        mma_bf16(o[mi][2*db+1], pa_h[mi], vh4 + 2);
                        mma_bf16(o[mi][2*db],   pa_h[mi], vl4);
                        mma_bf16(o[mi][2*db+1], pa_h[mi], vl4 + 2);
                        mma_bf16(o[mi][2*db],   pa_l[mi], vh4);
                        mma_bf16(o[mi][2*db+1], pa_l[mi], vh4 + 2);
                    }
                }
            }
        }

        __syncthreads();
        if (kt + 2 < nkt) load_stage(kt & 1, kt + 2);
        CP_COMMIT();
    }

    // ---- epilogue: normalize, write triple-interleaved A3 [b, s, 3*DM] ----
    const int b = bh >> 4, h = bh & 15;
    __nv_bfloat162* d2 = (__nv_bfloat162*)A3out;
    #pragma unroll
    for (int mi = 0; mi < 2; mi++) {
        const float inv0 = 1.0f / l_[mi][0], inv1 = 1.0f / l_[mi][1];
        const int srow0 = qbase + wid * 32 + mi * 16 + (lane >> 2);
        #pragma unroll
        for (int half = 0; half < 2; half++) {
            const int srow = srow0 + half * 8;
            const float inv = half ? inv1 : inv0;
            const size_t rbase = (size_t)(b * SEQ + srow) * (K3 / 2);
            #pragma unroll
            for (int ni = 0; ni < 8; ni++) {
                const int col = ni * 8 + ((lane & 3) << 1);
                const float x = o[mi][ni][half*2+0] * inv;
                const float y = o[mi][ni][half*2+1] * inv;
                bf16 hx = __float2bfloat16(x), hy = __float2bfloat16(y);
                bf16 lx = __float2bfloat16(x - __bfloat162float(hx));
                bf16 ly = __float2bfloat16(y - __bfloat162float(hy));
                const size_t kk = rbase + 3 * (size_t)(h * 32 + (col >> 1));
                d2[kk + 0] = __halves2bfloat162(hx, lx);
                d2[kk + 1] = __halves2bfloat162(hx, hy);
                d2[kk + 2] = __halves2bfloat162(ly, hy);
            }
        }
    }
}

// ---------------------------------------------------------------------------

extern "C" void kernel_launch(void* const* d_in, const int* in_sizes, int n_in,
                              void* d_out, int out_size)
{
    (void)in_sizes; (void)n_in; (void)out_size;
    const float* x  = (const float*)d_in[0];
    const float* wq = (const float*)d_in[1];
    const float* wk = (const float*)d_in[2];
    const float* wv = (const float*)d_in[3];
    const float* wo = (const float*)d_in[4];

    float *v;
    bf16 *x3, *w3, *a3, *qh, *ql, *kh, *kl, *vth, *vtl;
    cudaGetSymbolAddress((void**)&v,  g_V);
    cudaGetSymbolAddress((void**)&x3, g_X3);
    cudaGetSymbolAddress((void**)&w3, g_W3);
    cudaGetSymbolAddress((void**)&a3, g_A3);
    cudaGetSymbolAddress((void**)&qh, g_Qh);
    cudaGetSymbolAddress((void**)&ql, g_Ql);
    cudaGetSymbolAddress((void**)&kh, g_Kh);
    cudaGetSymbolAddress((void**)&kl, g_Kl);
    cudaGetSymbolAddress((void**)&vth, g_Vth);
    cudaGetSymbolAddress((void**)&vtl, g_Vtl);

    static bool attr_set = false;
    if (!attr_set) {
        cudaFuncSetAttribute(gemm_hmma<0>,
                             cudaFuncAttributeMaxDynamicSharedMemorySize, GEMM_SMEM);
        cudaFuncSetAttribute(gemm_hmma<1>,
                             cudaFuncAttributeMaxDynamicSharedMemorySize, GEMM_SMEM);
        cudaFuncSetAttribute(gemm_hmma<2>,
                             cudaFuncAttributeMaxDynamicSharedMemorySize, GEMM_SMEM);
        cudaFuncSetAttribute(flash_hmma,
                             cudaFuncAttributeMaxDynamicSharedMemorySize, FA_SMEM);
        attr_set = true;
    }

    // fp32 -> triple-interleaved bf16
    split3_a<<<1024, 256>>>(x, x3, MROWS * DM / 2);
    W4 ws; ws.p[0] = wq; ws.p[1] = wk; ws.p[2] = wv; ws.p[3] = wo;
    split3_w<<<dim3(128, 4), 256>>>(ws, w3);

    // QKV projections: Q/K emit scaled (hi,lo) bf16, V emits fp32 head layout
    dim3 blk(256);
    dim3 grid_g(DM / 128, MROWS / 256);     // (8, 16)
    gemm_hmma<2><<<grid_g, blk, GEMM_SMEM>>>(
        x3, w3 + 0 * (size_t)DM * K3, nullptr, qh, ql, 0.125f);
    gemm_hmma<2><<<grid_g, blk, GEMM_SMEM>>>(
        x3, w3 + 1 * (size_t)DM * K3, nullptr, kh, kl, 1.0f);
    gemm_hmma<1><<<grid_g, blk, GEMM_SMEM>>>(
        x3, w3 + 2 * (size_t)DM * K3, v, nullptr, nullptr, 1.0f);

    transpose_split_v<<<dim3(SEQ / 64, BATCH * NH), 256>>>(v, vth, vtl);

    // Tensor-core flash attention, emits triple-interleaved A3 directly
    flash_hmma<<<dim3(SEQ / 256, BATCH * NH), blk, FA_SMEM>>>(
        qh, ql, kh, kl, vth, vtl, a3);

    // O-projection
    gemm_hmma<0><<<grid_g, blk, GEMM_SMEM>>>(
        a3, w3 + 3 * (size_t)DM * K3, (float*)d_out, nullptr, nullptr, 1.0f);
}